// round 3
// baseline (speedup 1.0000x reference)
#include <cuda_runtime.h>
#include <cstdint>

// LSTM_10960756539796: B=256, T=512, D=64, H=256, C=10
// Persistent cluster kernel: 16 clusters x 8 CTAs x 512 threads.
//   cluster g -> batch rows [g*16, g*16+16)
//   rank   r -> hidden units [r*32, r*32+32)  (128 gate rows of W_hh/W_ih)
// W slices register-resident (fma.rn.f32x2 packed pairs). Per-step h exchange
// via st.async.shared::cluster + mbarrier (expect_tx), parity double-buffered.

#define TT    512
#define DD    64
#define HH    256
#define NRNK  8
#define BB    16
#define HU    32
#define NL    128
#define NTHR  512

typedef unsigned long long u64;

__device__ __forceinline__ u64 fma2(u64 a, u64 b, u64 c) {
    u64 d;
    asm("fma.rn.f32x2 %0, %1, %2, %3;" : "=l"(d) : "l"(a), "l"(b), "l"(c));
    return d;
}
__device__ __forceinline__ float hsum2(u64 v) {
    float lo, hi;
    asm("mov.b64 {%0,%1}, %2;" : "=f"(lo), "=f"(hi) : "l"(v));
    return lo + hi;
}
__device__ __forceinline__ uint32_t smem_u32(const void* p) {
    uint32_t a;
    asm("{ .reg .u64 t; cvta.to.shared.u64 t, %1; cvt.u32.u64 %0, t; }" : "=r"(a) : "l"(p));
    return a;
}
__device__ __forceinline__ void mbar_init(uint32_t m, uint32_t cnt) {
    asm volatile("mbarrier.init.shared.b64 [%0], %1;" :: "r"(m), "r"(cnt) : "memory");
}
__device__ __forceinline__ void mbar_arm(uint32_t m, uint32_t tx) {
    asm volatile("mbarrier.arrive.expect_tx.shared.b64 _, [%0], %1;" :: "r"(m), "r"(tx) : "memory");
}
__device__ __forceinline__ void mbar_wait_cluster(uint32_t m, uint32_t parity) {
    asm volatile(
        "{\n\t.reg .pred P;\n"
        "W%=:\n\t"
        "mbarrier.try_wait.parity.acquire.cluster.shared::cta.b64 P, [%0], %1, 0x989680;\n\t"
        "@!P bra W%=;\n\t}"
        :: "r"(m), "r"(parity) : "memory");
}
__device__ __forceinline__ uint32_t mapa_u32(uint32_t addr, int rank) {
    uint32_t out;
    asm("mapa.shared::cluster.u32 %0, %1, %2;" : "=r"(out) : "r"(addr), "r"(rank));
    return out;
}
__device__ __forceinline__ void st_async_b64(uint32_t raddr, u64 v, uint32_t rmbar) {
    asm volatile("st.async.weak.shared::cluster.mbarrier::complete_tx::bytes.b64 [%0], %1, [%2];"
                 :: "r"(raddr), "l"(v), "r"(rmbar) : "memory");
}

// dynamic smem layout (bytes)
#define OFF_H   0            // h_buf[2][BB][HH]  = 32768
#define OFF_X   32768        // x_sm [2][BB][DD]  =  8192
#define OFF_ZP  40960        // zp   [4][BB][NL]  = 32768
#define SMEM_BYTES 73728
#define HBUF_PAR 16384       // bytes per h parity buffer
#define HTX 16384            // expect_tx bytes per phase (8 ranks * 2048)

__global__ __launch_bounds__(NTHR, 1) __cluster_dims__(NRNK, 1, 1)
void lstm_cluster_kernel(const float* __restrict__ x,
                         const float* __restrict__ W_ih,
                         const float* __restrict__ W_hh,
                         const float* __restrict__ b_ih,
                         const float* __restrict__ b_hh,
                         const float* __restrict__ W_out,
                         const float* __restrict__ b_out,
                         float* __restrict__ out)
{
    extern __shared__ __align__(16) char smem_raw[];
    float (*h_buf)[BB][HH] = (float (*)[BB][HH])(smem_raw + OFF_H);
    float (*x_sm)[BB][DD]  = (float (*)[BB][DD])(smem_raw + OFF_X);
    float (*zp)[BB][NL]    = (float (*)[BB][NL])(smem_raw + OFF_ZP);
    __shared__ __align__(8) u64 mbars[2];

    const int g    = blockIdx.x >> 3;
    const int r    = blockIdx.x & 7;
    const int tid  = threadIdx.x;
    const int lane = tid & 31;
    const int n    = tid & 127;        // gate row (gate*32 + u)
    const int kq   = tid >> 7;         // k-quarter 0..3
    const int gate = n >> 5;
    const int u    = n & 31;
    const int nglob = gate * HH + r * HU + u;

    const uint32_t dyn_base = smem_u32(smem_raw);
    const uint32_t mbar_base = smem_u32(&mbars[0]);

    // ---- register-resident weights (packed k-pairs) ----
    u64 W2[32];
    {
        const u64* wp = (const u64*)(W_hh + (size_t)nglob * HH + kq * 64);
        #pragma unroll
        for (int i = 0; i < 32; i++) W2[i] = wp[i];
    }
    u64 Wi2[8];
    {
        const u64* wp = (const u64*)(W_ih + (size_t)nglob * DD + kq * 16);
        #pragma unroll
        for (int i = 0; i < 8; i++) Wi2[i] = wp[i];
    }
    const float bias = b_ih[nglob] + b_hh[nglob];   // applied by kq==0 only

    // cell owned by this thread: row cb = warp id, unit cu = lane
    const int cb = tid >> 5;
    const int cu = lane;
    float creg = 0.0f;

    // ---- init: zero h parity-0 buffer, init + arm both mbarriers ----
    for (int i = tid; i < BB * HH; i += NTHR) (&h_buf[0][0][0])[i] = 0.0f;
    if (tid == 0) {
        mbar_init(mbar_base + 0, 1);
        mbar_init(mbar_base + 8, 1);
        mbar_arm(mbar_base + 0, HTX);   // phase 0 of mbar[0] (first waited at t=2)
        mbar_arm(mbar_base + 8, HTX);   // phase 0 of mbar[1] (first waited at t=1)
        asm volatile("fence.mbarrier_init.release.cluster;" ::: "memory");
    }
    __syncthreads();
    asm volatile("barrier.cluster.arrive.aligned;" ::: "memory");
    asm volatile("barrier.cluster.wait.aligned;"   ::: "memory");

    const float* xbase = x + (size_t)(g * BB) * TT * DD;
    // x prefetch for t=0: thread covers flat indices tid and tid+512 of [BB][DD]
    const int xb0 = tid >> 6, xd0 = tid & 63;
    const int xb1 = (tid + 512) >> 6, xd1 = (tid + 512) & 63;
    float xr0 = xbase[((size_t)xb0 * TT + 0) * DD + xd0];
    float xr1 = xbase[((size_t)xb1 * TT + 0) * DD + xd1];

    uint32_t ph0 = 0, ph1 = 0;
    const int jj = lane & 15;           // b64 chunk index within the warp's row

    #pragma unroll 1
    for (int t = 0; t < TT; t++) {
        const int q  = t & 1;
        const int q2 = (t + 1) & 1;

        // stash prefetched x tile
        x_sm[q][xb0][xd0] = xr0;
        x_sm[q][xb1][xd1] = xr1;

        if (t > 0) {
            const uint32_t m = mbar_base + q * 8;
            mbar_wait_cluster(m, q ? ph1 : ph0);
            if (tid == 0) mbar_arm(m, HTX);           // re-arm next phase
            if (q) { if (tid == 0) {} ph1 ^= 1; } else { ph0 ^= 1; }
        }
        __syncthreads();   // x_sm ready; zp safe to overwrite

        // ---- GEMM partials: zp[kq][b][n] ----
        #pragma unroll 1
        for (int b = 0; b < BB; b++) {
            u64 a0 = 0, a1 = 0, a2 = 0, a3 = 0;
            const ulonglong2* hp = (const ulonglong2*)(&h_buf[q][b][kq * 64]);
            #pragma unroll
            for (int i = 0; i < 16; i += 2) {
                ulonglong2 v = hp[i];
                ulonglong2 w = hp[i + 1];
                a0 = fma2(W2[2 * i + 0], v.x, a0);
                a1 = fma2(W2[2 * i + 1], v.y, a1);
                a2 = fma2(W2[2 * i + 2], w.x, a2);
                a3 = fma2(W2[2 * i + 3], w.y, a3);
            }
            const ulonglong2* xp = (const ulonglong2*)(&x_sm[q][b][kq * 16]);
            #pragma unroll
            for (int i = 0; i < 4; i += 2) {
                ulonglong2 v = xp[i];
                ulonglong2 w = xp[i + 1];
                a0 = fma2(Wi2[2 * i + 0], v.x, a0);
                a1 = fma2(Wi2[2 * i + 1], v.y, a1);
                a2 = fma2(Wi2[2 * i + 2], w.x, a2);
                a3 = fma2(Wi2[2 * i + 3], w.y, a3);
            }
            float s = (hsum2(a0) + hsum2(a1)) + (hsum2(a2) + hsum2(a3));
            if (kq == 0) s += bias;
            zp[kq][b][n] = s;
        }
        __syncthreads();

        // ---- cell update (1 cell/thread) ----
        float zi = (zp[0][cb][cu]      + zp[1][cb][cu])      + (zp[2][cb][cu]      + zp[3][cb][cu]);
        float zf = (zp[0][cb][32 + cu] + zp[1][cb][32 + cu]) + (zp[2][cb][32 + cu] + zp[3][cb][32 + cu]);
        float zg = (zp[0][cb][64 + cu] + zp[1][cb][64 + cu]) + (zp[2][cb][64 + cu] + zp[3][cb][64 + cu]);
        float zo = (zp[0][cb][96 + cu] + zp[1][cb][96 + cu]) + (zp[2][cb][96 + cu] + zp[3][cb][96 + cu]);
        float si = 1.0f / (1.0f + __expf(-zi));
        float sf = 1.0f / (1.0f + __expf(-zf));
        float so = 1.0f / (1.0f + __expf(-zo));
        creg = sf * creg + si * tanhf(zg);
        float hval = so * tanhf(creg);

        // ---- broadcast h slice to all 8 cluster CTAs via st.async ----
        float plo = __shfl_sync(0xFFFFFFFFu, hval, 2 * jj);
        float phi = __shfl_sync(0xFFFFFFFFu, hval, 2 * jj + 1);
        u64 pk;
        asm("mov.b64 %0, {%1,%2};" : "=l"(pk) : "f"(plo), "f"(phi));
        if (lane < 16) {
            const uint32_t loff = dyn_base + OFF_H + (uint32_t)q2 * HBUF_PAR
                                + ((uint32_t)(cb * HH + r * HU + 2 * jj)) * 4u;
            const uint32_t lmb = mbar_base + (uint32_t)q2 * 8;
            #pragma unroll
            for (int p = 0; p < NRNK; p++) {
                st_async_b64(mapa_u32(loff, p), pk, mapa_u32(lmb, p));
            }
        }

        // ---- prefetch x for t+1 (overlaps DSMEM drain + next wait) ----
        if (t + 1 < TT) {
            xr0 = xbase[((size_t)xb0 * TT + (t + 1)) * DD + xd0];
            xr1 = xbase[((size_t)xb1 * TT + (t + 1)) * DD + xd1];
        }
    }

    // ---- head: rank 0 computes sigmoid(hT @ W_out^T + b_out) ----
    if (r == 0) {
        const int qf = TT & 1;   // = 0
        mbar_wait_cluster(mbar_base + qf * 8, ph0);
        if (tid < BB * 10) {
            int b = tid / 10, c = tid % 10;
            float acc = b_out[c];
            #pragma unroll 4
            for (int k = 0; k < HH; k++)
                acc = fmaf(h_buf[qf][b][k], W_out[c * HH + k], acc);
            out[(g * BB + b) * 10 + c] = 1.0f / (1.0f + __expf(-acc));
        }
    }

    // all CTAs stay alive until every peer is done receiving
    asm volatile("barrier.cluster.arrive.aligned;" ::: "memory");
    asm volatile("barrier.cluster.wait.aligned;"   ::: "memory");
}

extern "C" void kernel_launch(void* const* d_in, const int* in_sizes, int n_in,
                              void* d_out, int out_size)
{
    (void)in_sizes; (void)n_in; (void)out_size;
    const float* x     = (const float*)d_in[0];
    const float* W_ih  = (const float*)d_in[1];
    const float* W_hh  = (const float*)d_in[2];
    const float* b_ih  = (const float*)d_in[3];
    const float* b_hh  = (const float*)d_in[4];
    const float* W_out = (const float*)d_in[5];
    const float* b_out = (const float*)d_in[6];
    float* outp = (float*)d_out;

    cudaFuncSetAttribute(lstm_cluster_kernel,
                         cudaFuncAttributeMaxDynamicSharedMemorySize, SMEM_BYTES);
    lstm_cluster_kernel<<<16 * NRNK, NTHR, SMEM_BYTES>>>(
        x, W_ih, W_hh, b_ih, b_hh, W_out, b_out, outp);
}

// round 4
// speedup vs baseline: 1.0130x; 1.0130x over previous
#include <cuda_runtime.h>
#include <cstdint>

// LSTM_10960756539796: B=256, T=512, D=64, H=256, C=10
// Persistent cluster kernel: 16 clusters x 8 CTAs x 512 threads.
//   cluster g -> batch rows [g*16, g*16+16)
//   rank   r -> hidden units [r*32, r*32+32)  (128 gate rows of W_hh/W_ih)
// W slices register-resident (fma.rn.f32x2 packed k-pairs). Per-step h
// exchange: rank-major h layout, ONE cp.async.bulk (2KB) per peer per step,
// mbarrier expect_tx = 7*2KB, parity double-buffered.

#define TT    512
#define DD    64
#define HH    256
#define NRNK  8
#define BB    16
#define HU    32
#define NL    128
#define NTHR  512

typedef unsigned long long u64;

__device__ __forceinline__ u64 fma2(u64 a, u64 b, u64 c) {
    u64 d;
    asm("fma.rn.f32x2 %0, %1, %2, %3;" : "=l"(d) : "l"(a), "l"(b), "l"(c));
    return d;
}
__device__ __forceinline__ float hsum2(u64 v) {
    float lo, hi;
    asm("mov.b64 {%0,%1}, %2;" : "=f"(lo), "=f"(hi) : "l"(v));
    return lo + hi;
}
__device__ __forceinline__ uint32_t smem_u32(const void* p) {
    uint32_t a;
    asm("{ .reg .u64 t; cvta.to.shared.u64 t, %1; cvt.u32.u64 %0, t; }" : "=r"(a) : "l"(p));
    return a;
}
__device__ __forceinline__ void mbar_init(uint32_t m, uint32_t cnt) {
    asm volatile("mbarrier.init.shared.b64 [%0], %1;" :: "r"(m), "r"(cnt) : "memory");
}
__device__ __forceinline__ void mbar_arm(uint32_t m, uint32_t tx) {
    asm volatile("mbarrier.arrive.expect_tx.shared.b64 _, [%0], %1;" :: "r"(m), "r"(tx) : "memory");
}
__device__ __forceinline__ void mbar_wait(uint32_t m, uint32_t parity) {
    asm volatile(
        "{\n\t.reg .pred P;\n"
        "W%=:\n\t"
        "mbarrier.try_wait.parity.acquire.cluster.shared::cta.b64 P, [%0], %1, 0x989680;\n\t"
        "@!P bra W%=;\n\t}"
        :: "r"(m), "r"(parity) : "memory");
}
__device__ __forceinline__ uint32_t mapa_u32(uint32_t addr, int rank) {
    uint32_t out;
    asm("mapa.shared::cluster.u32 %0, %1, %2;" : "=r"(out) : "r"(addr), "r"(rank));
    return out;
}
__device__ __forceinline__ void bulk_dsmem(uint32_t dst_cluster, uint32_t src_cta,
                                           uint32_t bytes, uint32_t mbar_cluster) {
    asm volatile("cp.async.bulk.shared::cluster.shared::cta.mbarrier::complete_tx::bytes "
                 "[%0], [%1], %2, [%3];"
                 :: "r"(dst_cluster), "r"(src_cta), "r"(bytes), "r"(mbar_cluster) : "memory");
}

// dynamic smem layout (bytes)
#define OFF_H   0            // h_rm[2][NRNK][BB][HU] = 32768 (rank-major!)
#define OFF_X   32768        // x_sm[2][BB][DD]       =  8192
#define OFF_ZP  40960        // zp  [4][BB][NL]       = 32768
#define SMEM_BYTES 73728
#define HBUF_PAR 16384       // bytes per parity buffer
#define SLICE    2048        // bytes per rank slice (16*32*4)
#define HTX      (7 * SLICE) // expect_tx: 7 peers (self via STS)

__global__ __launch_bounds__(NTHR, 1) __cluster_dims__(NRNK, 1, 1)
void lstm_cluster_kernel(const float* __restrict__ x,
                         const float* __restrict__ W_ih,
                         const float* __restrict__ W_hh,
                         const float* __restrict__ b_ih,
                         const float* __restrict__ b_hh,
                         const float* __restrict__ W_out,
                         const float* __restrict__ b_out,
                         float* __restrict__ out)
{
    extern __shared__ __align__(16) char smem_raw[];
    // h_rm[parity][rank][b][u]
    float (*h_rm)[NRNK][BB][HU] = (float (*)[NRNK][BB][HU])(smem_raw + OFF_H);
    float (*x_sm)[BB][DD]       = (float (*)[BB][DD])(smem_raw + OFF_X);
    float (*zp)[BB][NL]         = (float (*)[BB][NL])(smem_raw + OFF_ZP);
    __shared__ __align__(8) u64 mbars[2];

    const int g    = blockIdx.x >> 3;
    const int r    = blockIdx.x & 7;
    const int tid  = threadIdx.x;
    const int lane = tid & 31;
    const int n    = tid & 127;        // gate row (gate*32 + u)
    const int kq   = tid >> 7;         // k-quarter 0..3 (k in [kq*64, kq*64+64))
    const int gate = n >> 5;
    const int u    = n & 31;
    const int nglob = gate * HH + r * HU + u;

    const uint32_t dyn_base  = smem_u32(smem_raw);
    const uint32_t mbar_base = smem_u32(&mbars[0]);

    // ---- register-resident weights (packed k-pairs) ----
    u64 W2[32];
    {
        const u64* wp = (const u64*)(W_hh + (size_t)nglob * HH + kq * 64);
        #pragma unroll
        for (int i = 0; i < 32; i++) W2[i] = wp[i];
    }
    u64 Wi2[8];
    {
        const u64* wp = (const u64*)(W_ih + (size_t)nglob * DD + kq * 16);
        #pragma unroll
        for (int i = 0; i < 8; i++) Wi2[i] = wp[i];
    }
    const float bias = b_ih[nglob] + b_hh[nglob];   // applied by kq==0 only

    // cell owned by this thread: batch row cb = warp id, unit cu = lane
    const int cb = tid >> 5;
    const int cu = lane;
    float creg = 0.0f;

    // ---- init: zero parity-0 h, init + pre-arm both mbarriers ----
    for (int i = tid; i < NRNK * BB * HU; i += NTHR) (&h_rm[0][0][0][0])[i] = 0.0f;
    if (tid == 0) {
        mbar_init(mbar_base + 0, 1);
        mbar_init(mbar_base + 8, 1);
        mbar_arm(mbar_base + 0, HTX);   // phase 0: receives sends of t=1
        mbar_arm(mbar_base + 8, HTX);   // phase 0: receives sends of t=0
        asm volatile("fence.mbarrier_init.release.cluster;" ::: "memory");
    }
    __syncthreads();
    asm volatile("barrier.cluster.arrive.aligned;" ::: "memory");
    asm volatile("barrier.cluster.wait.aligned;"   ::: "memory");

    const float* xbase = x + (size_t)(g * BB) * TT * DD;
    const int xb0 = tid >> 6,         xd0 = tid & 63;
    const int xb1 = (tid + 512) >> 6, xd1 = (tid + 512) & 63;
    float xr0 = xbase[((size_t)xb0 * TT + 0) * DD + xd0];
    float xr1 = xbase[((size_t)xb1 * TT + 0) * DD + xd1];

    // peer for warp-0 lanes 0..6 (skip self)
    const int peer = lane + (lane >= r ? 1 : 0);

    #pragma unroll 1
    for (int t = 0; t < TT; t++) {
        const int q  = t & 1;
        const int q2 = (t + 1) & 1;

        // stash prefetched x tile
        x_sm[q][xb0][xd0] = xr0;
        x_sm[q][xb1][xd1] = xr1;

        if (t > 0) {
            if (tid == 0) {
                const uint32_t m  = mbar_base + (uint32_t)q * 8;
                const uint32_t ph = ((uint32_t)(t - 1) >> 1) & 1;
                mbar_wait(m, ph);
                mbar_arm(m, HTX);   // re-arm before our sends this step (ordering via bar below)
            }
        }
        __syncthreads();   // x_sm + full h_rm[q] visible to all

        // ---- GEMM partials: zp[kq][b][n] over k in [kq*64, kq*64+64) ----
        #pragma unroll 1
        for (int b = 0; b < BB; b++) {
            u64 a0 = 0, a1 = 0, a2 = 0, a3 = 0;
            const ulonglong2* hA = (const ulonglong2*)(&h_rm[q][2 * kq + 0][b][0]);
            const ulonglong2* hB = (const ulonglong2*)(&h_rm[q][2 * kq + 1][b][0]);
            #pragma unroll
            for (int i = 0; i < 8; i += 2) {
                ulonglong2 v = hA[i], w = hA[i + 1];
                a0 = fma2(W2[2 * i + 0], v.x, a0);
                a1 = fma2(W2[2 * i + 1], v.y, a1);
                a2 = fma2(W2[2 * i + 2], w.x, a2);
                a3 = fma2(W2[2 * i + 3], w.y, a3);
            }
            #pragma unroll
            for (int i = 0; i < 8; i += 2) {
                ulonglong2 v = hB[i], w = hB[i + 1];
                a0 = fma2(W2[16 + 2 * i + 0], v.x, a0);
                a1 = fma2(W2[16 + 2 * i + 1], v.y, a1);
                a2 = fma2(W2[16 + 2 * i + 2], w.x, a2);
                a3 = fma2(W2[16 + 2 * i + 3], w.y, a3);
            }
            const ulonglong2* xp = (const ulonglong2*)(&x_sm[q][b][kq * 16]);
            #pragma unroll
            for (int i = 0; i < 4; i += 2) {
                ulonglong2 v = xp[i], w = xp[i + 1];
                a0 = fma2(Wi2[2 * i + 0], v.x, a0);
                a1 = fma2(Wi2[2 * i + 1], v.y, a1);
                a2 = fma2(Wi2[2 * i + 2], w.x, a2);
                a3 = fma2(Wi2[2 * i + 3], w.y, a3);
            }
            float s = (hsum2(a0) + hsum2(a1)) + (hsum2(a2) + hsum2(a3));
            if (kq == 0) s += bias;
            zp[kq][b][n] = s;
        }
        __syncthreads();

        // ---- cell update (1 cell/thread), store own slice locally ----
        {
            float zi = (zp[0][cb][cu]      + zp[1][cb][cu])      + (zp[2][cb][cu]      + zp[3][cb][cu]);
            float zf = (zp[0][cb][32 + cu] + zp[1][cb][32 + cu]) + (zp[2][cb][32 + cu] + zp[3][cb][32 + cu]);
            float zg = (zp[0][cb][64 + cu] + zp[1][cb][64 + cu]) + (zp[2][cb][64 + cu] + zp[3][cb][64 + cu]);
            float zo = (zp[0][cb][96 + cu] + zp[1][cb][96 + cu]) + (zp[2][cb][96 + cu] + zp[3][cb][96 + cu]);
            float si = 1.0f / (1.0f + __expf(-zi));
            float sf = 1.0f / (1.0f + __expf(-zf));
            float so = 1.0f / (1.0f + __expf(-zo));
            creg = sf * creg + si * tanhf(zg);
            h_rm[q2][r][cb][cu] = so * tanhf(creg);
        }
        asm volatile("fence.proxy.async.shared::cta;" ::: "memory");
        __syncthreads();   // slice complete + proxy-visible; re-arm done before sends

        // ---- ONE bulk DSMEM copy per peer (warp 0, lanes 0..6) ----
        if (tid < 7) {
            const uint32_t src  = dyn_base + OFF_H + (uint32_t)q2 * HBUF_PAR + (uint32_t)r * SLICE;
            const uint32_t lmb  = mbar_base + (uint32_t)q2 * 8;
            bulk_dsmem(mapa_u32(src, peer), src, SLICE, mapa_u32(lmb, peer));
        }

        // ---- prefetch x for t+1 (overlaps DSMEM transit) ----
        if (t + 1 < TT) {
            xr0 = xbase[((size_t)xb0 * TT + (t + 1)) * DD + xd0];
            xr1 = xbase[((size_t)xb1 * TT + (t + 1)) * DD + xd1];
        }
    }

    // ---- head: rank 0 computes sigmoid(hT @ W_out^T + b_out) ----
    if (r == 0) {
        if (tid == 0) {
            // final h lands in parity 0; its wait phase continues the t-sequence
            const uint32_t ph = ((uint32_t)(TT - 1) >> 1) & 1;
            mbar_wait(mbar_base + 0, ph);
        }
        __syncthreads();
        if (tid < BB * 10) {
            int b = tid / 10, c = tid % 10;
            float acc = b_out[c];
            #pragma unroll 4
            for (int k = 0; k < HH; k++)
                acc = fmaf(h_rm[0][k >> 5][b][k & 31], W_out[c * HH + k], acc);
            out[(g * BB + b) * 10 + c] = 1.0f / (1.0f + __expf(-acc));
        }
    }

    // no CTA exits while peers' bulk copies to it may be in flight
    asm volatile("barrier.cluster.arrive.aligned;" ::: "memory");
    asm volatile("barrier.cluster.wait.aligned;"   ::: "memory");
}

extern "C" void kernel_launch(void* const* d_in, const int* in_sizes, int n_in,
                              void* d_out, int out_size)
{
    (void)in_sizes; (void)n_in; (void)out_size;
    const float* x     = (const float*)d_in[0];
    const float* W_ih  = (const float*)d_in[1];
    const float* W_hh  = (const float*)d_in[2];
    const float* b_ih  = (const float*)d_in[3];
    const float* b_hh  = (const float*)d_in[4];
    const float* W_out = (const float*)d_in[5];
    const float* b_out = (const float*)d_in[6];
    float* outp = (float*)d_out;

    cudaFuncSetAttribute(lstm_cluster_kernel,
                         cudaFuncAttributeMaxDynamicSharedMemorySize, SMEM_BYTES);
    lstm_cluster_kernel<<<16 * NRNK, NTHR, SMEM_BYTES>>>(
        x, W_ih, W_hh, b_ih, b_hh, W_out, b_out, outp);
}

// round 5
// speedup vs baseline: 1.7701x; 1.7473x over previous
#include <cuda_runtime.h>
#include <cstdint>

// LSTM_10960756539796: B=256, T=512, D=64, H=256, C=10
// Persistent kernel, 128 CTAs x 512 threads (no clusters).
//   group g = blockIdx/8 -> batch rows [g*16, g*16+16)
//   rank  r = blockIdx%8 -> hidden units [r*32, r*32+32) (128 gate rows)
// W register-resident (fma.rn.f32x2 packed k-pairs). h exchange via L2 with
// step-indexed release/acquire flags (no atomics, no per-thread fences).

#define TT    512
#define DD    64
#define HH    256
#define NGRP  16
#define NRNK  8
#define BB    16
#define HU    32
#define NL    128
#define NTHR  512

typedef unsigned long long u64;

__device__ float g_H[2][256][HH];          // [parity][b][k]
__device__ int   g_flagT[NGRP][TT][NRNK];  // set-once per run, reset at end
__device__ int   g_done[NGRP];

__device__ __forceinline__ u64 fma2(u64 a, u64 b, u64 c) {
    u64 d;
    asm("fma.rn.f32x2 %0, %1, %2, %3;" : "=l"(d) : "l"(a), "l"(b), "l"(c));
    return d;
}
__device__ __forceinline__ float hsum2(u64 v) {
    float lo, hi;
    asm("mov.b64 {%0,%1}, %2;" : "=f"(lo), "=f"(hi) : "l"(v));
    return lo + hi;
}
__device__ __forceinline__ float4 ldcv4(const float* p) {
    float4 v;
    asm volatile("ld.volatile.global.v4.f32 {%0,%1,%2,%3}, [%4];"
                 : "=f"(v.x), "=f"(v.y), "=f"(v.z), "=f"(v.w) : "l"(p));
    return v;
}
__device__ __forceinline__ void stcg(float* p, float v) {
    asm volatile("st.global.cg.f32 [%0], %1;" :: "l"(p), "f"(v));
}
__device__ __forceinline__ int ldacq(const int* p) {
    int v;
    asm volatile("ld.acquire.gpu.global.b32 %0, [%1];" : "=r"(v) : "l"(p));
    return v;
}
__device__ __forceinline__ void strel(int* p, int v) {
    asm volatile("st.release.gpu.global.b32 [%0], %1;" :: "l"(p), "r"(v));
}

__global__ __launch_bounds__(NTHR, 1)
void lstm_persistent_kernel(const float* __restrict__ x,
                            const float* __restrict__ W_ih,
                            const float* __restrict__ W_hh,
                            const float* __restrict__ b_ih,
                            const float* __restrict__ b_hh,
                            const float* __restrict__ W_out,
                            const float* __restrict__ b_out,
                            float* __restrict__ out)
{
    extern __shared__ __align__(16) char smem_raw[];
    float (*h_sm)[HH]   = (float (*)[HH])(smem_raw);             // 16 KB
    float (*x_sm)[DD]   = (float (*)[DD])(smem_raw + 16384);     //  4 KB
    float (*zp)[BB][NL] = (float (*)[BB][NL])(smem_raw + 20480); // 32 KB

    const int g    = blockIdx.x >> 3;
    const int r    = blockIdx.x & 7;
    const int tid  = threadIdx.x;
    const int lane = tid & 31;
    const int wid  = tid >> 5;
    const int n    = tid & 127;        // gate row (gate*32 + u)
    const int kq   = tid >> 7;         // k-quarter 0..3
    const int gate = n >> 5;
    const int u    = n & 31;
    const int nglob = gate * HH + r * HU + u;

    // ---- register-resident weights (packed k-pairs) ----
    u64 W2[32];
    {
        const u64* wp = (const u64*)(W_hh + (size_t)nglob * HH + kq * 64);
        #pragma unroll
        for (int i = 0; i < 32; i++) W2[i] = wp[i];
    }
    u64 Wi2[8];
    {
        const u64* wp = (const u64*)(W_ih + (size_t)nglob * DD + kq * 16);
        #pragma unroll
        for (int i = 0; i < 8; i++) Wi2[i] = wp[i];
    }
    const float bias = b_ih[nglob] + b_hh[nglob];   // applied by kq==0 only

    // cell owned by this thread: batch row cb = warp id, unit cu = lane
    const int cb = tid >> 5;
    const int cu = lane;
    float creg = 0.0f;

    for (int i = tid; i < BB * HH; i += NTHR) (&h_sm[0][0])[i] = 0.0f;
    __syncthreads();

    const float* xbase = x + (size_t)(g * BB) * TT * DD;
    const int xb0 = tid >> 6,         xd0 = tid & 63;
    const int xb1 = (tid + 512) >> 6, xd1 = (tid + 512) & 63;
    float xr0 = xbase[((size_t)xb0 * TT + 0) * DD + xd0];
    float xr1 = xbase[((size_t)xb1 * TT + 0) * DD + xd1];

    // h copy addressing: thread covers 8 consecutive floats (2x float4)
    float* hdst = &h_sm[0][0] + tid * 8;

    #pragma unroll 1
    for (int t = 0; t < TT; t++) {
        const int q = t & 1;

        // stash prefetched x tile
        x_sm[xb0][xd0] = xr0;
        x_sm[xb1][xd1] = xr1;

        if (t > 0) {
            // warp 0 lanes 0..7 each poll one rank's flag (acquire), ballot until all set
            if (wid == 0) {
                int ready = (lane < NRNK) ? 0 : 1;
                const int* fp = &g_flagT[g][t - 1][lane & 7];
                while (__ballot_sync(0xFFFFFFFFu, ready) != 0xFFFFFFFFu) {
                    if (!ready && ldacq(fp) != 0) ready = 1;
                }
            }
        }
        __syncthreads();                    // poll done; x_sm visible; prev-step smem free
        if (t > 0) {
            const float* src = &g_H[q][g * BB][0] + tid * 8;
            float4 v0 = ldcv4(src);
            float4 v1 = ldcv4(src + 4);
            *(float4*)(hdst)     = v0;
            *(float4*)(hdst + 4) = v1;
        }
        __syncthreads();                    // h_sm ready

        // ---- GEMM partials: zp[kq][b][n] ----
        #pragma unroll 1
        for (int b = 0; b < BB; b++) {
            u64 a0 = 0, a1 = 0, a2 = 0, a3 = 0;
            const ulonglong2* hp = (const ulonglong2*)(&h_sm[b][kq * 64]);
            #pragma unroll
            for (int i = 0; i < 16; i += 2) {
                ulonglong2 v = hp[i];
                ulonglong2 w = hp[i + 1];
                a0 = fma2(W2[2 * i + 0], v.x, a0);
                a1 = fma2(W2[2 * i + 1], v.y, a1);
                a2 = fma2(W2[2 * i + 2], w.x, a2);
                a3 = fma2(W2[2 * i + 3], w.y, a3);
            }
            const ulonglong2* xp = (const ulonglong2*)(&x_sm[b][kq * 16]);
            #pragma unroll
            for (int i = 0; i < 4; i += 2) {
                ulonglong2 v = xp[i];
                ulonglong2 w = xp[i + 1];
                a0 = fma2(Wi2[2 * i + 0], v.x, a0);
                a1 = fma2(Wi2[2 * i + 1], v.y, a1);
                a2 = fma2(Wi2[2 * i + 2], w.x, a2);
                a3 = fma2(Wi2[2 * i + 3], w.y, a3);
            }
            float s = (hsum2(a0) + hsum2(a1)) + (hsum2(a2) + hsum2(a3));
            if (kq == 0) s += bias;
            zp[kq][b][n] = s;
        }
        __syncthreads();

        // prefetch x for t+1 (LDG latency overlaps cell + barriers + next poll)
        if (t + 1 < TT) {
            xr0 = xbase[((size_t)xb0 * TT + (t + 1)) * DD + xd0];
            xr1 = xbase[((size_t)xb1 * TT + (t + 1)) * DD + xd1];
        }

        // ---- cell update (1 cell/thread) -> g_H[(t+1)&1] ----
        {
            float zi = (zp[0][cb][cu]      + zp[1][cb][cu])      + (zp[2][cb][cu]      + zp[3][cb][cu]);
            float zf = (zp[0][cb][32 + cu] + zp[1][cb][32 + cu]) + (zp[2][cb][32 + cu] + zp[3][cb][32 + cu]);
            float zg = (zp[0][cb][64 + cu] + zp[1][cb][64 + cu]) + (zp[2][cb][64 + cu] + zp[3][cb][64 + cu]);
            float zo = (zp[0][cb][96 + cu] + zp[1][cb][96 + cu]) + (zp[2][cb][96 + cu] + zp[3][cb][96 + cu]);
            float si = 1.0f / (1.0f + __expf(-zi));
            float sf = 1.0f / (1.0f + __expf(-zf));
            float so = 1.0f / (1.0f + __expf(-zo));
            creg = sf * creg + si * tanhf(zg);
            stcg(&g_H[(t + 1) & 1][g * BB + cb][r * HU + cu], so * tanhf(creg));
        }
        __syncthreads();                    // all h stores issued before release
        if (tid == 0) strel(&g_flagT[g][t][r], 1);   // single release-store (grid-sync pattern)
    }

    // ---- head: rank 0 computes sigmoid(hT @ W_out^T + b_out) ----
    if (r == 0) {
        if (wid == 0) {
            int ready = (lane < NRNK) ? 0 : 1;
            const int* fp = &g_flagT[g][TT - 1][lane & 7];
            while (__ballot_sync(0xFFFFFFFFu, ready) != 0xFFFFFFFFu) {
                if (!ready && ldacq(fp) != 0) ready = 1;
            }
        }
        __syncthreads();
        {
            const float* src = &g_H[0][g * BB][0] + tid * 8;   // TT&1 == 0
            float4 v0 = ldcv4(src);
            float4 v1 = ldcv4(src + 4);
            *(float4*)(hdst)     = v0;
            *(float4*)(hdst + 4) = v1;
        }
        __syncthreads();
        if (tid < BB * 10) {
            int b = tid / 10, c = tid % 10;
            float acc = b_out[c];
            #pragma unroll 4
            for (int k = 0; k < HH; k++)
                acc = fmaf(h_sm[b][k], W_out[c * HH + k], acc);
            out[(g * BB + b) * 10 + c] = 1.0f / (1.0f + __expf(-acc));
        }
    }

    // ---- end protocol: after all ranks finished polling, rank 0 resets flags ----
    __syncthreads();
    if (tid == 0) atomicAdd(&g_done[g], 1);
    if (r == 0) {
        if (tid == 0) {
            while (ldacq(&g_done[g]) < NRNK) { }
        }
        __syncthreads();
        int* fl = &g_flagT[g][0][0];
        for (int i = tid; i < TT * NRNK; i += NTHR) fl[i] = 0;
        __syncthreads();
        if (tid == 0) { __threadfence(); g_done[g] = 0; }
    }
}

extern "C" void kernel_launch(void* const* d_in, const int* in_sizes, int n_in,
                              void* d_out, int out_size)
{
    (void)in_sizes; (void)n_in; (void)out_size;
    const float* x     = (const float*)d_in[0];
    const float* W_ih  = (const float*)d_in[1];
    const float* W_hh  = (const float*)d_in[2];
    const float* b_ih  = (const float*)d_in[3];
    const float* b_hh  = (const float*)d_in[4];
    const float* W_out = (const float*)d_in[5];
    const float* b_out = (const float*)d_in[6];
    float* outp = (float*)d_out;

    const int smem_bytes = 16384 + 4096 + 32768;   // 52 KB
    cudaFuncSetAttribute(lstm_persistent_kernel,
                         cudaFuncAttributeMaxDynamicSharedMemorySize, smem_bytes);
    lstm_persistent_kernel<<<NGRP * NRNK, NTHR, smem_bytes>>>(
        x, W_ih, W_hh, b_ih, b_hh, W_out, b_out, outp);
}

// round 6
// speedup vs baseline: 2.1453x; 1.2120x over previous
#include <cuda_runtime.h>
#include <cstdint>

// LSTM_10960756539796: B=256, T=512, D=64, H=256, C=10
// Persistent kernel, 128 CTAs x 512 threads.
//   group g = blockIdx/8 -> batch rows [g*16, g*16+16)
//   rank  r = blockIdx%8 -> hidden units [r*32, r*32+32) (128 gate rows)
// Thread split: kh = tid>>6 (k-eighth, 32 k's), np = tid&63 (row pair 2np,2np+1).
// Each LDS.128 of h feeds 8 FFMA2 (2 rows) -> halved L1 wavefront load vs R5.
// h exchange via L2 step-indexed release/acquire flags (R5 scheme, proven).

#define TT    512
#define DD    64
#define HH    256
#define NGRP  16
#define NRNK  8
#define BB    16
#define HU    32
#define NL    128
#define NTHR  512
#define NKH   8

typedef unsigned long long u64;

__device__ float g_H[2][256][HH];          // [parity][b][k]
__device__ int   g_flagT[NGRP][TT][NRNK];  // set-once per run, reset at end
__device__ int   g_done[NGRP];

__device__ __forceinline__ u64 fma2(u64 a, u64 b, u64 c) {
    u64 d;
    asm("fma.rn.f32x2 %0, %1, %2, %3;" : "=l"(d) : "l"(a), "l"(b), "l"(c));
    return d;
}
__device__ __forceinline__ float hsum2(u64 v) {
    float lo, hi;
    asm("mov.b64 {%0,%1}, %2;" : "=f"(lo), "=f"(hi) : "l"(v));
    return lo + hi;
}
__device__ __forceinline__ float4 ldcv4(const float* p) {
    float4 v;
    asm volatile("ld.volatile.global.v4.f32 {%0,%1,%2,%3}, [%4];"
                 : "=f"(v.x), "=f"(v.y), "=f"(v.z), "=f"(v.w) : "l"(p));
    return v;
}
__device__ __forceinline__ void stcg(float* p, float v) {
    asm volatile("st.global.cg.f32 [%0], %1;" :: "l"(p), "f"(v));
}
__device__ __forceinline__ int ldacq(const int* p) {
    int v;
    asm volatile("ld.acquire.gpu.global.b32 %0, [%1];" : "=r"(v) : "l"(p));
    return v;
}
__device__ __forceinline__ void strel(int* p, int v) {
    asm volatile("st.release.gpu.global.b32 [%0], %1;" :: "l"(p), "r"(v));
}

// dynamic smem layout
#define OFF_H  0        // h_sm[BB][HH]      = 16384
#define OFF_X  16384    // x_sm[BB][DD]      =  4096
#define OFF_ZP 20480    // zp[NKH][BB][NL]   = 65536
#define SMEM_BYTES 86016

__global__ __launch_bounds__(NTHR, 1)
void lstm_persistent_kernel(const float* __restrict__ x,
                            const float* __restrict__ W_ih,
                            const float* __restrict__ W_hh,
                            const float* __restrict__ b_ih,
                            const float* __restrict__ b_hh,
                            const float* __restrict__ W_out,
                            const float* __restrict__ b_out,
                            float* __restrict__ out)
{
    extern __shared__ __align__(16) char smem_raw[];
    float (*h_sm)[HH]        = (float (*)[HH])(smem_raw + OFF_H);
    float (*x_sm)[DD]        = (float (*)[DD])(smem_raw + OFF_X);
    float (*zp)[BB][NL]      = (float (*)[BB][NL])(smem_raw + OFF_ZP);

    const int g    = blockIdx.x >> 3;
    const int r    = blockIdx.x & 7;
    const int tid  = threadIdx.x;
    const int lane = tid & 31;
    const int wid  = tid >> 5;
    const int kh   = tid >> 6;          // k-eighth: k in [kh*32, kh*32+32)
    const int np   = tid & 63;          // row pair: rows 2np, 2np+1
    const int row0 = 2 * np;            // even -> both rows same gate
    const int gate = row0 >> 5;
    const int u0   = row0 & 31;
    const int nglob0 = gate * HH + r * HU + u0;
    const int nglob1 = nglob0 + 1;

    // ---- register-resident weights (packed k-pairs), 2 rows x 32 k ----
    u64 W2[32];
    {
        const u64* wp0 = (const u64*)(W_hh + (size_t)nglob0 * HH + kh * 32);
        const u64* wp1 = (const u64*)(W_hh + (size_t)nglob1 * HH + kh * 32);
        #pragma unroll
        for (int i = 0; i < 16; i++) W2[i]      = wp0[i];
        #pragma unroll
        for (int i = 0; i < 16; i++) W2[16 + i] = wp1[i];
    }
    u64 Wi2[8];
    {
        const u64* wp0 = (const u64*)(W_ih + (size_t)nglob0 * DD + kh * 8);
        const u64* wp1 = (const u64*)(W_ih + (size_t)nglob1 * DD + kh * 8);
        #pragma unroll
        for (int i = 0; i < 4; i++) Wi2[i]     = wp0[i];
        #pragma unroll
        for (int i = 0; i < 4; i++) Wi2[4 + i] = wp1[i];
    }
    const float bias0 = b_ih[nglob0] + b_hh[nglob0];  // applied by kh==0 only
    const float bias1 = b_ih[nglob1] + b_hh[nglob1];

    // cell owned by this thread: batch row cb = warp id, unit cu = lane
    const int cb = wid;
    const int cu = lane;
    float creg = 0.0f;

    for (int i = tid; i < BB * HH; i += NTHR) (&h_sm[0][0])[i] = 0.0f;
    __syncthreads();

    const float* xbase = x + (size_t)(g * BB) * TT * DD;
    const int xb0 = tid >> 6,         xd0 = tid & 63;
    const int xb1 = (tid + 512) >> 6, xd1 = (tid + 512) & 63;
    float xr0 = xbase[((size_t)xb0 * TT + 0) * DD + xd0];
    float xr1 = xbase[((size_t)xb1 * TT + 0) * DD + xd1];

    // h copy addressing: thread covers 8 consecutive floats (2x float4)
    float* hdst = &h_sm[0][0] + tid * 8;

    #pragma unroll 1
    for (int t = 0; t < TT; t++) {
        const int q = t & 1;

        // stash prefetched x tile
        x_sm[xb0][xd0] = xr0;
        x_sm[xb1][xd1] = xr1;

        if (t > 0) {
            if (wid == 0) {
                int ready = (lane < NRNK) ? 0 : 1;
                const int* fp = &g_flagT[g][t - 1][lane & 7];
                while (__ballot_sync(0xFFFFFFFFu, ready) != 0xFFFFFFFFu) {
                    if (!ready && ldacq(fp) != 0) ready = 1;
                }
            }
        }
        __syncthreads();                    // poll done; x_sm visible; smem free
        if (t > 0) {
            const float* src = &g_H[q][g * BB][0] + tid * 8;
            float4 v0 = ldcv4(src);
            float4 v1 = ldcv4(src + 4);
            *(float4*)(hdst)     = v0;
            *(float4*)(hdst + 4) = v1;
        }
        __syncthreads();                    // h_sm ready

        // ---- GEMM partials: 2 rows x 32 k per thread ----
        #pragma unroll 1
        for (int b = 0; b < BB; b++) {
            u64 a0 = 0, a1 = 0, c0 = 0, c1 = 0;
            const ulonglong2* hp = (const ulonglong2*)(&h_sm[b][kh * 32]);
            #pragma unroll
            for (int i = 0; i < 8; i++) {
                ulonglong2 v = hp[i];
                a0 = fma2(W2[2 * i + 0],      v.x, a0);
                a1 = fma2(W2[2 * i + 1],      v.y, a1);
                c0 = fma2(W2[16 + 2 * i + 0], v.x, c0);
                c1 = fma2(W2[16 + 2 * i + 1], v.y, c1);
            }
            const ulonglong2* xp = (const ulonglong2*)(&x_sm[b][kh * 8]);
            #pragma unroll
            for (int i = 0; i < 2; i++) {
                ulonglong2 v = xp[i];
                a0 = fma2(Wi2[2 * i + 0],     v.x, a0);
                a1 = fma2(Wi2[2 * i + 1],     v.y, a1);
                c0 = fma2(Wi2[4 + 2 * i + 0], v.x, c0);
                c1 = fma2(Wi2[4 + 2 * i + 1], v.y, c1);
            }
            float s0 = hsum2(a0) + hsum2(a1);
            float s1 = hsum2(c0) + hsum2(c1);
            if (kh == 0) { s0 += bias0; s1 += bias1; }
            *(float2*)(&zp[kh][b][row0]) = make_float2(s0, s1);
        }
        __syncthreads();

        // prefetch x for t+1 (LDG latency overlaps cell + barriers + next poll)
        if (t + 1 < TT) {
            xr0 = xbase[((size_t)xb0 * TT + (t + 1)) * DD + xd0];
            xr1 = xbase[((size_t)xb1 * TT + (t + 1)) * DD + xd1];
        }

        // ---- cell update (1 cell/thread): sum 8 k-partials per gate ----
        {
            float zi = 0.0f, zf = 0.0f, zg = 0.0f, zo = 0.0f;
            #pragma unroll
            for (int k2 = 0; k2 < NKH; k2++) {
                zi += zp[k2][cb][cu];
                zf += zp[k2][cb][32 + cu];
                zg += zp[k2][cb][64 + cu];
                zo += zp[k2][cb][96 + cu];
            }
            float si = 1.0f / (1.0f + __expf(-zi));
            float sf = 1.0f / (1.0f + __expf(-zf));
            float so = 1.0f / (1.0f + __expf(-zo));
            creg = sf * creg + si * tanhf(zg);
            stcg(&g_H[(t + 1) & 1][g * BB + cb][r * HU + cu], so * tanhf(creg));
        }
        __syncthreads();                    // all h stores issued before release
        if (tid == 0) strel(&g_flagT[g][t][r], 1);
    }

    // ---- head: rank 0 computes sigmoid(hT @ W_out^T + b_out) ----
    if (r == 0) {
        if (wid == 0) {
            int ready = (lane < NRNK) ? 0 : 1;
            const int* fp = &g_flagT[g][TT - 1][lane & 7];
            while (__ballot_sync(0xFFFFFFFFu, ready) != 0xFFFFFFFFu) {
                if (!ready && ldacq(fp) != 0) ready = 1;
            }
        }
        __syncthreads();
        {
            const float* src = &g_H[0][g * BB][0] + tid * 8;   // TT&1 == 0
            float4 v0 = ldcv4(src);
            float4 v1 = ldcv4(src + 4);
            *(float4*)(hdst)     = v0;
            *(float4*)(hdst + 4) = v1;
        }
        __syncthreads();
        if (tid < BB * 10) {
            int b = tid / 10, c = tid % 10;
            float acc = b_out[c];
            #pragma unroll 4
            for (int k = 0; k < HH; k++)
                acc = fmaf(h_sm[b][k], W_out[c * HH + k], acc);
            out[(g * BB + b) * 10 + c] = 1.0f / (1.0f + __expf(-acc));
        }
    }

    // ---- end protocol: after all ranks finish polling, rank 0 resets flags ----
    __syncthreads();
    if (tid == 0) atomicAdd(&g_done[g], 1);
    if (r == 0) {
        if (tid == 0) {
            while (ldacq(&g_done[g]) < NRNK) { }
        }
        __syncthreads();
        int* fl = &g_flagT[g][0][0];
        for (int i = tid; i < TT * NRNK; i += NTHR) fl[i] = 0;
        __syncthreads();
        if (tid == 0) { __threadfence(); g_done[g] = 0; }
    }
}

extern "C" void kernel_launch(void* const* d_in, const int* in_sizes, int n_in,
                              void* d_out, int out_size)
{
    (void)in_sizes; (void)n_in; (void)out_size;
    const float* x     = (const float*)d_in[0];
    const float* W_ih  = (const float*)d_in[1];
    const float* W_hh  = (const float*)d_in[2];
    const float* b_ih  = (const float*)d_in[3];
    const float* b_hh  = (const float*)d_in[4];
    const float* W_out = (const float*)d_in[5];
    const float* b_out = (const float*)d_in[6];
    float* outp = (float*)d_out;

    cudaFuncSetAttribute(lstm_persistent_kernel,
                         cudaFuncAttributeMaxDynamicSharedMemorySize, SMEM_BYTES);
    lstm_persistent_kernel<<<NGRP * NRNK, NTHR, SMEM_BYTES>>>(
        x, W_ih, W_hh, b_ih, b_hh, W_out, b_out, outp);
}